// round 1
// baseline (speedup 1.0000x reference)
#include <cuda_runtime.h>

#define BATCH  8
#define NPTS   4096
#define TPB    128
#define ITILES (NPTS / TPB)   // 32 blocks of queries per (batch, direction)
#define JTILE  512            // shared tile of target points (8 KB as float4)

// Per-block partial sums: [dir][batch][itile]
__device__ float g_part[2 * BATCH * ITILES];

// One direction per blockIdx.z: dir 0 = x->y mins, dir 1 = y->x mins.
// Each thread owns one query point i, scans all 4096 target points via a
// shared float4 tile (qx,qy,qz, q2), keeping 4 independent min accumulators
// for ILP across the FFMA dependency chains.
__global__ __launch_bounds__(TPB) void chamfer_min_kernel(
    const float* __restrict__ A, const float* __restrict__ Bp)
{
    const int dir = blockIdx.z;
    const int b   = blockIdx.y;
    const float* __restrict__ xb = (dir == 0 ? A : Bp) + (size_t)b * NPTS * 3;
    const float* __restrict__ yb = (dir == 0 ? Bp : A) + (size_t)b * NPTS * 3;

    const int i = blockIdx.x * TPB + threadIdx.x;
    const float px = xb[3 * i + 0];
    const float py = xb[3 * i + 1];
    const float pz = xb[3 * i + 2];
    const float p2 = fmaf(px, px, fmaf(py, py, pz * pz));

    __shared__ float4 tile[JTILE];

    float m0 = 3.0e38f, m1 = 3.0e38f, m2 = 3.0e38f, m3 = 3.0e38f;

    for (int t = 0; t < NPTS; t += JTILE) {
        // Cooperative tile load: pack (q, ||q||^2) into float4 for one LDS.128
        #pragma unroll
        for (int k = threadIdx.x; k < JTILE; k += TPB) {
            const float qx = yb[3 * (t + k) + 0];
            const float qy = yb[3 * (t + k) + 1];
            const float qz = yb[3 * (t + k) + 2];
            tile[k] = make_float4(qx, qy, qz, fmaf(qx, qx, fmaf(qy, qy, qz * qz)));
        }
        __syncthreads();

        #pragma unroll 8
        for (int j = 0; j < JTILE; j += 4) {
            const float4 q0 = tile[j + 0];
            const float4 q1 = tile[j + 1];
            const float4 q2 = tile[j + 2];
            const float4 q3 = tile[j + 3];
            // v = q2 - 2*(p . q); min_j(d2) = p2 + min_j(v), clamp at end.
            float d0 = fmaf(pz, q0.z, fmaf(py, q0.y, px * q0.x));
            float d1 = fmaf(pz, q1.z, fmaf(py, q1.y, px * q1.x));
            float d2 = fmaf(pz, q2.z, fmaf(py, q2.y, px * q2.x));
            float d3 = fmaf(pz, q3.z, fmaf(py, q3.y, px * q3.x));
            m0 = fminf(m0, fmaf(-2.0f, d0, q0.w));
            m1 = fminf(m1, fmaf(-2.0f, d1, q1.w));
            m2 = fminf(m2, fmaf(-2.0f, d2, q2.w));
            m3 = fminf(m3, fmaf(-2.0f, d3, q3.w));
        }
        __syncthreads();
    }

    // max(d2,0) commutes with min (monotone), so clamp the final min.
    float val = fmaxf(p2 + fminf(fminf(m0, m1), fminf(m2, m3)), 0.0f);

    // Deterministic block reduction: warp shuffle tree + fixed-order warp sums
    #pragma unroll
    for (int o = 16; o > 0; o >>= 1)
        val += __shfl_down_sync(0xffffffffu, val, o);

    __shared__ float wsum[TPB / 32];
    if ((threadIdx.x & 31) == 0) wsum[threadIdx.x >> 5] = val;
    __syncthreads();
    if (threadIdx.x == 0) {
        float s = 0.0f;
        #pragma unroll
        for (int w = 0; w < TPB / 32; w++) s += wsum[w];
        g_part[(dir * BATCH + b) * ITILES + blockIdx.x] = s;
    }
}

// Final deterministic reduction of 512 partials -> scalar mean.
__global__ void chamfer_reduce_kernel(float* __restrict__ out)
{
    const int n = 2 * BATCH * ITILES;  // 512
    float v = 0.0f;
    // fixed order: thread t sums elements t, t+128, t+256, t+384
    #pragma unroll
    for (int k = threadIdx.x; k < n; k += 128) v += g_part[k];

    #pragma unroll
    for (int o = 16; o > 0; o >>= 1)
        v += __shfl_down_sync(0xffffffffu, v, o);

    __shared__ float wsum[4];
    if ((threadIdx.x & 31) == 0) wsum[threadIdx.x >> 5] = v;
    __syncthreads();
    if (threadIdx.x == 0) {
        float s = wsum[0] + wsum[1] + wsum[2] + wsum[3];
        out[0] = s / (float)(BATCH * NPTS);
    }
}

extern "C" void kernel_launch(void* const* d_in, const int* in_sizes, int n_in,
                              void* d_out, int out_size)
{
    const float* A  = (const float*)d_in[0];  // coor_recon [8,4096,3]
    const float* Bp = (const float*)d_in[1];  // pc_gd      [8,4096,3]
    float* out = (float*)d_out;

    dim3 grid(ITILES, BATCH, 2);
    chamfer_min_kernel<<<grid, TPB>>>(A, Bp);
    chamfer_reduce_kernel<<<1, 128>>>(out);
}

// round 2
// speedup vs baseline: 1.3285x; 1.3285x over previous
#include <cuda_runtime.h>

#define BATCH  8
#define NPTS   4096
#define TPB    64          // 2 warps per block -> fine-grained wave balance (512 blocks)
#define QPT    2           // queries per thread
#define QPB    (TPB * QPT) // 128 queries per block
#define ITILES (NPTS / QPB)// 32
#define JTILE  1024        // SoA target tile: 4 arrays * 4KB = 16KB smem
#define NPART  (2 * BATCH * ITILES) // 512 partials

__device__ float        g_part[NPART];
__device__ unsigned int g_count; // zero-initialized at load; self-resetting

// ---- packed f32x2 helpers (Blackwell; PTX-only) ----
__device__ __forceinline__ unsigned long long bcast2(float v) {
    unsigned long long r;
    asm("mov.b64 %0, {%1, %1};" : "=l"(r) : "f"(v));
    return r;
}
__device__ __forceinline__ unsigned long long fma2(unsigned long long a,
                                                   unsigned long long b,
                                                   unsigned long long c) {
    unsigned long long d;
    asm("fma.rn.f32x2 %0, %1, %2, %3;" : "=l"(d) : "l"(a), "l"(b), "l"(c));
    return d;
}
__device__ __forceinline__ void unpack2(unsigned long long v, float& lo, float& hi) {
    asm("mov.b64 {%0, %1}, %2;" : "=f"(lo), "=f"(hi) : "l"(v));
}

// dir 0: queries=A targets=B ; dir 1: queries=B targets=A.
// Each thread owns 2 query points; targets streamed through SoA smem tiles as
// packed f32x2 pairs. min_j d2 = p2 + min_j(w_j - 2 p.q_j), clamp at the end.
__global__ __launch_bounds__(TPB) void chamfer_kernel(
    const float* __restrict__ A, const float* __restrict__ Bp,
    float* __restrict__ out)
{
    const int dir = blockIdx.z;
    const int b   = blockIdx.y;
    const float* __restrict__ xb = (dir == 0 ? A : Bp) + (size_t)b * NPTS * 3;
    const float* __restrict__ yb = (dir == 0 ? Bp : A) + (size_t)b * NPTS * 3;

    // Two queries per thread
    const int iA = blockIdx.x * QPB + threadIdx.x;
    const int iB = iA + TPB;
    const float pAx = xb[3 * iA + 0], pAy = xb[3 * iA + 1], pAz = xb[3 * iA + 2];
    const float pBx = xb[3 * iB + 0], pBy = xb[3 * iB + 1], pBz = xb[3 * iB + 2];
    const float p2A = fmaf(pAx, pAx, fmaf(pAy, pAy, pAz * pAz));
    const float p2B = fmaf(pBx, pBx, fmaf(pBy, pBy, pBz * pBz));
    // fold the -2 into the query coords: t = fma(n,q,w) == w - 2 p.q
    const unsigned long long nAx = bcast2(-2.0f * pAx);
    const unsigned long long nAy = bcast2(-2.0f * pAy);
    const unsigned long long nAz = bcast2(-2.0f * pAz);
    const unsigned long long nBx = bcast2(-2.0f * pBx);
    const unsigned long long nBy = bcast2(-2.0f * pBy);
    const unsigned long long nBz = bcast2(-2.0f * pBz);

    __shared__ __align__(16) float xs[JTILE], ys[JTILE], zs[JTILE], ws[JTILE];

    float mA0 = 3.0e38f, mA1 = 3.0e38f, mA2 = 3.0e38f, mA3 = 3.0e38f;
    float mB0 = 3.0e38f, mB1 = 3.0e38f, mB2 = 3.0e38f, mB3 = 3.0e38f;

    for (int t = 0; t < NPTS; t += JTILE) {
        for (int k = threadIdx.x; k < JTILE; k += TPB) {
            const float qx = yb[3 * (t + k) + 0];
            const float qy = yb[3 * (t + k) + 1];
            const float qz = yb[3 * (t + k) + 2];
            xs[k] = qx; ys[k] = qy; zs[k] = qz;
            ws[k] = fmaf(qx, qx, fmaf(qy, qy, qz * qz));
        }
        __syncthreads();

        const ulonglong2* __restrict__ X4 = (const ulonglong2*)xs;
        const ulonglong2* __restrict__ Y4 = (const ulonglong2*)ys;
        const ulonglong2* __restrict__ Z4 = (const ulonglong2*)zs;
        const ulonglong2* __restrict__ W4 = (const ulonglong2*)ws;

        #pragma unroll 4
        for (int j = 0; j < JTILE / 4; j++) {
            const ulonglong2 xv = X4[j];   // {x0,x1},{x2,x3} packed f32x2
            const ulonglong2 yv = Y4[j];
            const ulonglong2 zv = Z4[j];
            const ulonglong2 wv = W4[j];

            const unsigned long long tA01 = fma2(nAx, xv.x, fma2(nAy, yv.x, fma2(nAz, zv.x, wv.x)));
            const unsigned long long tA23 = fma2(nAx, xv.y, fma2(nAy, yv.y, fma2(nAz, zv.y, wv.y)));
            const unsigned long long tB01 = fma2(nBx, xv.x, fma2(nBy, yv.x, fma2(nBz, zv.x, wv.x)));
            const unsigned long long tB23 = fma2(nBx, xv.y, fma2(nBy, yv.y, fma2(nBz, zv.y, wv.y)));

            float t0, t1, t2, t3;
            unpack2(tA01, t0, t1); unpack2(tA23, t2, t3);
            mA0 = fminf(mA0, t0); mA1 = fminf(mA1, t1);
            mA2 = fminf(mA2, t2); mA3 = fminf(mA3, t3);
            unpack2(tB01, t0, t1); unpack2(tB23, t2, t3);
            mB0 = fminf(mB0, t0); mB1 = fminf(mB1, t1);
            mB2 = fminf(mB2, t2); mB3 = fminf(mB3, t3);
        }
        __syncthreads();
    }

    // max(d2,0) commutes with min -> clamp final value only
    float val = fmaxf(p2A + fminf(fminf(mA0, mA1), fminf(mA2, mA3)), 0.0f)
              + fmaxf(p2B + fminf(fminf(mB0, mB1), fminf(mB2, mB3)), 0.0f);

    // Deterministic block reduction (2 warps)
    #pragma unroll
    for (int o = 16; o > 0; o >>= 1)
        val += __shfl_down_sync(0xffffffffu, val, o);

    __shared__ float wsum[TPB / 32];
    __shared__ int   is_last;
    if ((threadIdx.x & 31) == 0) wsum[threadIdx.x >> 5] = val;
    __syncthreads();

    if (threadIdx.x == 0) {
        float s = 0.0f;
        #pragma unroll
        for (int w = 0; w < TPB / 32; w++) s += wsum[w];
        g_part[(dir * BATCH + b) * ITILES + blockIdx.x] = s;
        __threadfence();
        unsigned int old = atomicAdd(&g_count, 1u);
        is_last = (old == NPART - 1) ? 1 : 0;
    }
    __syncthreads();

    // Last block performs the deterministic final reduction (fixed order).
    if (is_last) {
        float v = 0.0f;
        #pragma unroll
        for (int k = threadIdx.x; k < NPART; k += TPB) v += g_part[k];
        #pragma unroll
        for (int o = 16; o > 0; o >>= 1)
            v += __shfl_down_sync(0xffffffffu, v, o);
        if ((threadIdx.x & 31) == 0) wsum[threadIdx.x >> 5] = v;
        __syncthreads();
        if (threadIdx.x == 0) {
            out[0] = (wsum[0] + wsum[1]) / (float)(BATCH * NPTS);
            g_count = 0;  // reset for next graph replay
        }
    }
}

extern "C" void kernel_launch(void* const* d_in, const int* in_sizes, int n_in,
                              void* d_out, int out_size)
{
    const float* A  = (const float*)d_in[0];  // coor_recon [8,4096,3]
    const float* Bp = (const float*)d_in[1];  // pc_gd      [8,4096,3]
    float* out = (float*)d_out;

    dim3 grid(ITILES, BATCH, 2);
    chamfer_kernel<<<grid, TPB>>>(A, Bp, out);
}

// round 3
// speedup vs baseline: 1.7678x; 1.3307x over previous
#include <cuda_runtime.h>

#define BATCH  8
#define NPTS   4096
#define TPB    64
#define QPT    2
#define QPB    (TPB * QPT)       // 128 queries per block
#define ITILES (NPTS / QPB)      // 32
#define NSPLIT 4                 // target-dim splits -> 2048 blocks, 4096 warps
#define CHUNK  (NPTS / NSPLIT)   // 1024 targets per block
#define JTILE  512               // smem tile: 4 arrays * 2KB = 8KB
#define NQ     (2 * BATCH * NPTS)          // 65536 queries (both dirs)
#define CBLK   16                // combine blocks
#define CTPB   256

__device__ float        g_qmin[NQ * NSPLIT];   // [query][split], float4 per query
__device__ float        g_cpart[CBLK];
__device__ unsigned int g_count;               // zero-init; self-resetting

// ---- packed f32x2 helpers (Blackwell; PTX-only) ----
__device__ __forceinline__ unsigned long long bcast2(float v) {
    unsigned long long r;
    asm("mov.b64 %0, {%1, %1};" : "=l"(r) : "f"(v));
    return r;
}
__device__ __forceinline__ unsigned long long fma2(unsigned long long a,
                                                   unsigned long long b,
                                                   unsigned long long c) {
    unsigned long long d;
    asm("fma.rn.f32x2 %0, %1, %2, %3;" : "=l"(d) : "l"(a), "l"(b), "l"(c));
    return d;
}
__device__ __forceinline__ void unpack2(unsigned long long v, float& lo, float& hi) {
    asm("mov.b64 {%0, %1}, %2;" : "=f"(lo), "=f"(hi) : "l"(v));
}

// grid: (ITILES, BATCH, 2*NSPLIT). z: dir = z&1, split = z>>1.
// Each thread owns 2 query points and scans a 1024-target chunk through a
// SoA smem tile using packed f32x2 FMAs. Writes p2 + min_chunk(w - 2 p.q)
// (unclamped) to its [query][split] slot.
__global__ __launch_bounds__(TPB) void chamfer_kernel(
    const float* __restrict__ A, const float* __restrict__ Bp)
{
    const int dir   = blockIdx.z & 1;
    const int split = blockIdx.z >> 1;
    const int b     = blockIdx.y;
    const float* __restrict__ xb = (dir == 0 ? A : Bp) + (size_t)b * NPTS * 3;
    const float* __restrict__ yb = (dir == 0 ? Bp : A) + (size_t)b * NPTS * 3;

    const int iA = blockIdx.x * QPB + threadIdx.x;
    const int iB = iA + TPB;
    const float pAx = xb[3 * iA + 0], pAy = xb[3 * iA + 1], pAz = xb[3 * iA + 2];
    const float pBx = xb[3 * iB + 0], pBy = xb[3 * iB + 1], pBz = xb[3 * iB + 2];
    const float p2A = fmaf(pAx, pAx, fmaf(pAy, pAy, pAz * pAz));
    const float p2B = fmaf(pBx, pBx, fmaf(pBy, pBy, pBz * pBz));
    const unsigned long long nAx = bcast2(-2.0f * pAx);
    const unsigned long long nAy = bcast2(-2.0f * pAy);
    const unsigned long long nAz = bcast2(-2.0f * pAz);
    const unsigned long long nBx = bcast2(-2.0f * pBx);
    const unsigned long long nBy = bcast2(-2.0f * pBy);
    const unsigned long long nBz = bcast2(-2.0f * pBz);

    __shared__ __align__(16) float xs[JTILE], ys[JTILE], zs[JTILE], ws[JTILE];

    float mA0 = 3.0e38f, mA1 = 3.0e38f, mA2 = 3.0e38f, mA3 = 3.0e38f;
    float mB0 = 3.0e38f, mB1 = 3.0e38f, mB2 = 3.0e38f, mB3 = 3.0e38f;

    const int t0 = split * CHUNK;
    for (int t = t0; t < t0 + CHUNK; t += JTILE) {
        #pragma unroll
        for (int k = threadIdx.x; k < JTILE; k += TPB) {
            const float qx = yb[3 * (t + k) + 0];
            const float qy = yb[3 * (t + k) + 1];
            const float qz = yb[3 * (t + k) + 2];
            xs[k] = qx; ys[k] = qy; zs[k] = qz;
            ws[k] = fmaf(qx, qx, fmaf(qy, qy, qz * qz));
        }
        __syncthreads();

        const ulonglong2* __restrict__ X4 = (const ulonglong2*)xs;
        const ulonglong2* __restrict__ Y4 = (const ulonglong2*)ys;
        const ulonglong2* __restrict__ Z4 = (const ulonglong2*)zs;
        const ulonglong2* __restrict__ W4 = (const ulonglong2*)ws;

        #pragma unroll 4
        for (int j = 0; j < JTILE / 4; j++) {
            const ulonglong2 xv = X4[j];
            const ulonglong2 yv = Y4[j];
            const ulonglong2 zv = Z4[j];
            const ulonglong2 wv = W4[j];

            const unsigned long long tA01 = fma2(nAx, xv.x, fma2(nAy, yv.x, fma2(nAz, zv.x, wv.x)));
            const unsigned long long tA23 = fma2(nAx, xv.y, fma2(nAy, yv.y, fma2(nAz, zv.y, wv.y)));
            const unsigned long long tB01 = fma2(nBx, xv.x, fma2(nBy, yv.x, fma2(nBz, zv.x, wv.x)));
            const unsigned long long tB23 = fma2(nBx, xv.y, fma2(nBy, yv.y, fma2(nBz, zv.y, wv.y)));

            float u0, u1, u2, u3;
            unpack2(tA01, u0, u1); unpack2(tA23, u2, u3);
            mA0 = fminf(mA0, u0); mA1 = fminf(mA1, u1);
            mA2 = fminf(mA2, u2); mA3 = fminf(mA3, u3);
            unpack2(tB01, u0, u1); unpack2(tB23, u2, u3);
            mB0 = fminf(mB0, u0); mB1 = fminf(mB1, u1);
            mB2 = fminf(mB2, u2); mB3 = fminf(mB3, u3);
        }
        __syncthreads();
    }

    const float vA = p2A + fminf(fminf(mA0, mA1), fminf(mA2, mA3));
    const float vB = p2B + fminf(fminf(mB0, mB1), fminf(mB2, mB3));

    const size_t qbase = (size_t)(dir * BATCH + b) * NPTS;
    g_qmin[(qbase + iA) * NSPLIT + split] = vA;
    g_qmin[(qbase + iB) * NSPLIT + split] = vB;
}

// Combine: min across the 4 splits per query, clamp, deterministic mean.
__global__ __launch_bounds__(CTPB) void combine_kernel(float* __restrict__ out)
{
    const float4* __restrict__ Q = (const float4*)g_qmin;
    float s = 0.0f;
    // fixed traversal order: q = tid_global + k*4096  (NQ / (CBLK*CTPB) = 16)
    const int q0 = blockIdx.x * CTPB + threadIdx.x;
    #pragma unroll
    for (int k = 0; k < NQ / (CBLK * CTPB); k++) {
        const float4 v = Q[q0 + k * CBLK * CTPB];
        s += fmaxf(fminf(fminf(v.x, v.y), fminf(v.z, v.w)), 0.0f);
    }

    #pragma unroll
    for (int o = 16; o > 0; o >>= 1)
        s += __shfl_down_sync(0xffffffffu, s, o);

    __shared__ float wsum[CTPB / 32];
    __shared__ int   is_last;
    if ((threadIdx.x & 31) == 0) wsum[threadIdx.x >> 5] = s;
    __syncthreads();

    if (threadIdx.x == 0) {
        float ps = 0.0f;
        #pragma unroll
        for (int w = 0; w < CTPB / 32; w++) ps += wsum[w];
        g_cpart[blockIdx.x] = ps;
        __threadfence();
        unsigned int old = atomicAdd(&g_count, 1u);
        is_last = (old == CBLK - 1) ? 1 : 0;
    }
    __syncthreads();

    if (is_last && threadIdx.x == 0) {
        float tot = 0.0f;
        #pragma unroll
        for (int k = 0; k < CBLK; k++) tot += g_cpart[k];
        out[0] = tot / (float)(BATCH * NPTS);
        g_count = 0;  // reset for next graph replay
    }
}

extern "C" void kernel_launch(void* const* d_in, const int* in_sizes, int n_in,
                              void* d_out, int out_size)
{
    const float* A  = (const float*)d_in[0];  // coor_recon [8,4096,3]
    const float* Bp = (const float*)d_in[1];  // pc_gd      [8,4096,3]
    float* out = (float*)d_out;

    dim3 grid(ITILES, BATCH, 2 * NSPLIT);     // 2048 blocks
    chamfer_kernel<<<grid, TPB>>>(A, Bp);
    combine_kernel<<<CBLK, CTPB>>>(out);
}

// round 4
// speedup vs baseline: 1.8481x; 1.0454x over previous
#include <cuda_runtime.h>

#define BATCH  8
#define NPTS   4096
#define TPB    64
#define QPT    4
#define QPB    (TPB * QPT)       // 256 queries per block
#define ITILES (NPTS / QPB)      // 16
#define NSPLIT 16                // target splits -> fine-grain blocks
#define CHUNK  (NPTS / NSPLIT)   // 256 targets per block (single smem tile)
#define NQ     (2 * BATCH * NPTS)            // 65536 queries (both dirs)
#define CBLK   256
#define CTPB   256

__device__ float        g_qmin[NQ * NSPLIT]; // [query][split] -> 4 x float4
__device__ float        g_cpart[CBLK];
__device__ unsigned int g_count;             // zero-init; self-resetting

// ---- packed f32x2 helpers (Blackwell; PTX-only) ----
__device__ __forceinline__ unsigned long long bcast2(float v) {
    unsigned long long r;
    asm("mov.b64 %0, {%1, %1};" : "=l"(r) : "f"(v));
    return r;
}
__device__ __forceinline__ unsigned long long fma2(unsigned long long a,
                                                   unsigned long long b,
                                                   unsigned long long c) {
    unsigned long long d;
    asm("fma.rn.f32x2 %0, %1, %2, %3;" : "=l"(d) : "l"(a), "l"(b), "l"(c));
    return d;
}
__device__ __forceinline__ void unpack2(unsigned long long v, float& lo, float& hi) {
    asm("mov.b64 {%0, %1}, %2;" : "=f"(lo), "=f"(hi) : "l"(v));
}

// grid (ITILES, BATCH, 2*NSPLIT); z: dir = z&1, split = z>>1.
// Each thread owns 4 query points, scans one 256-target smem tile (loaded
// once, one barrier). Writes p2 + min_chunk(w - 2 p.q) per [query][split].
__global__ __launch_bounds__(TPB) void chamfer_kernel(
    const float* __restrict__ A, const float* __restrict__ Bp)
{
    const int dir   = blockIdx.z & 1;
    const int split = blockIdx.z >> 1;
    const int b     = blockIdx.y;
    const float* __restrict__ xb = (dir == 0 ? A : Bp) + (size_t)b * NPTS * 3;
    const float* __restrict__ yb = (dir == 0 ? Bp : A) + (size_t)b * NPTS * 3;

    __shared__ __align__(16) float xs[CHUNK], ys[CHUNK], zs[CHUNK], ws[CHUNK];

    // ---- load the target tile (once) ----
    const int t0 = split * CHUNK;
    #pragma unroll
    for (int k = threadIdx.x; k < CHUNK; k += TPB) {
        const float qx = yb[3 * (t0 + k) + 0];
        const float qy = yb[3 * (t0 + k) + 1];
        const float qz = yb[3 * (t0 + k) + 2];
        xs[k] = qx; ys[k] = qy; zs[k] = qz;
        ws[k] = fmaf(qx, qx, fmaf(qy, qy, qz * qz));
    }

    // ---- load 4 query points, fold -2 into packed broadcasts ----
    const int iBase = blockIdx.x * QPB + threadIdx.x;
    float p2[QPT];
    unsigned long long nx[QPT], ny[QPT], nz[QPT];
    #pragma unroll
    for (int q = 0; q < QPT; q++) {
        const int i = iBase + q * TPB;
        const float px = xb[3 * i + 0];
        const float py = xb[3 * i + 1];
        const float pz = xb[3 * i + 2];
        p2[q] = fmaf(px, px, fmaf(py, py, pz * pz));
        nx[q] = bcast2(-2.0f * px);
        ny[q] = bcast2(-2.0f * py);
        nz[q] = bcast2(-2.0f * pz);
    }

    __syncthreads();

    float m0[QPT], m1[QPT], m2[QPT], m3[QPT];
    #pragma unroll
    for (int q = 0; q < QPT; q++) { m0[q] = m1[q] = m2[q] = m3[q] = 3.0e38f; }

    const ulonglong2* __restrict__ X4 = (const ulonglong2*)xs;
    const ulonglong2* __restrict__ Y4 = (const ulonglong2*)ys;
    const ulonglong2* __restrict__ Z4 = (const ulonglong2*)zs;
    const ulonglong2* __restrict__ W4 = (const ulonglong2*)ws;

    #pragma unroll 4
    for (int j = 0; j < CHUNK / 4; j++) {
        const ulonglong2 xv = X4[j];   // {x0,x1},{x2,x3} packed f32x2
        const ulonglong2 yv = Y4[j];
        const ulonglong2 zv = Z4[j];
        const ulonglong2 wv = W4[j];

        #pragma unroll
        for (int q = 0; q < QPT; q++) {
            const unsigned long long t01 =
                fma2(nx[q], xv.x, fma2(ny[q], yv.x, fma2(nz[q], zv.x, wv.x)));
            const unsigned long long t23 =
                fma2(nx[q], xv.y, fma2(ny[q], yv.y, fma2(nz[q], zv.y, wv.y)));
            float u0, u1, u2, u3;
            unpack2(t01, u0, u1); unpack2(t23, u2, u3);
            m0[q] = fminf(m0[q], u0); m1[q] = fminf(m1[q], u1);
            m2[q] = fminf(m2[q], u2); m3[q] = fminf(m3[q], u3);
        }
    }

    const size_t qbase = (size_t)(dir * BATCH + b) * NPTS;
    #pragma unroll
    for (int q = 0; q < QPT; q++) {
        const float v = p2[q] + fminf(fminf(m0[q], m1[q]), fminf(m2[q], m3[q]));
        g_qmin[(qbase + iBase + q * TPB) * NSPLIT + split] = v;
    }
}

// Combine: min across 16 splits per query, clamp, deterministic mean.
__global__ __launch_bounds__(CTPB) void combine_kernel(float* __restrict__ out)
{
    const float4* __restrict__ Q = (const float4*)g_qmin;
    const int q = blockIdx.x * CTPB + threadIdx.x;   // one query per thread

    const float4 v0 = Q[q * 4 + 0];
    const float4 v1 = Q[q * 4 + 1];
    const float4 v2 = Q[q * 4 + 2];
    const float4 v3 = Q[q * 4 + 3];
    float mn = fminf(fminf(fminf(v0.x, v0.y), fminf(v0.z, v0.w)),
                     fminf(fminf(v1.x, v1.y), fminf(v1.z, v1.w)));
    mn = fminf(mn, fminf(fminf(fminf(v2.x, v2.y), fminf(v2.z, v2.w)),
                         fminf(fminf(v3.x, v3.y), fminf(v3.z, v3.w))));
    float s = fmaxf(mn, 0.0f);

    #pragma unroll
    for (int o = 16; o > 0; o >>= 1)
        s += __shfl_down_sync(0xffffffffu, s, o);

    __shared__ float wsum[CTPB / 32];
    __shared__ int   is_last;
    if ((threadIdx.x & 31) == 0) wsum[threadIdx.x >> 5] = s;
    __syncthreads();

    if (threadIdx.x == 0) {
        float ps = 0.0f;
        #pragma unroll
        for (int w = 0; w < CTPB / 32; w++) ps += wsum[w];
        g_cpart[blockIdx.x] = ps;
        __threadfence();
        unsigned int old = atomicAdd(&g_count, 1u);
        is_last = (old == CBLK - 1) ? 1 : 0;
    }
    __syncthreads();

    // Last block: parallel deterministic reduction of the 256 partials.
    if (is_last) {
        float v = g_cpart[threadIdx.x];   // CBLK == CTPB
        #pragma unroll
        for (int o = 16; o > 0; o >>= 1)
            v += __shfl_down_sync(0xffffffffu, v, o);
        if ((threadIdx.x & 31) == 0) wsum[threadIdx.x >> 5] = v;
        __syncthreads();
        if (threadIdx.x == 0) {
            float tot = 0.0f;
            #pragma unroll
            for (int w = 0; w < CTPB / 32; w++) tot += wsum[w];
            out[0] = tot / (float)(BATCH * NPTS);
            g_count = 0;  // reset for next graph replay
        }
    }
}

extern "C" void kernel_launch(void* const* d_in, const int* in_sizes, int n_in,
                              void* d_out, int out_size)
{
    const float* A  = (const float*)d_in[0];  // coor_recon [8,4096,3]
    const float* Bp = (const float*)d_in[1];  // pc_gd      [8,4096,3]
    float* out = (float*)d_out;

    dim3 grid(ITILES, BATCH, 2 * NSPLIT);     // 4096 blocks
    chamfer_kernel<<<grid, TPB>>>(A, Bp);
    combine_kernel<<<CBLK, CTPB>>>(out);
}